// round 12
// baseline (speedup 1.0000x reference)
#include <cuda_runtime.h>
#include <cuda_bf16.h>
#include <math.h>
#include <stdint.h>

#define BB 64
#define TT 256
#define CC 1024
#define HH 16
#define HD 64
#define MM (BB*TT)      /* 16384 rows */
#define EPSQ 1e-5f

/* ------------------------- scratch (static device globals) ----------------- */
__device__ float          g_wmean[4];
__device__ double         g_partial[4*64];
__device__ __nv_bfloat16  g_wq[4][CC*CC];
__device__ __nv_bfloat16  g_xq[MM*CC];
__device__ float          g_ascale[MM];
__device__ __nv_bfloat16  g_qhi[MM*CC];
__device__ __nv_bfloat16  g_qlo[MM*CC];
__device__ __nv_bfloat16  g_khi[MM*CC];
__device__ __nv_bfloat16  g_klo[MM*CC];
__device__ __nv_bfloat16  g_vhi[MM*CC];
__device__ __nv_bfloat16  g_vlo[MM*CC];
__device__ float          g_yb[MM*CC];
__device__ __nv_bfloat16  g_yq[MM*CC];
__device__ float          g_yscale[MM];

/* ------------------------- PTX helpers ------------------------------------ */
__device__ __forceinline__ void cp16(uint32_t smem_u32, const void* gmem)
{
    asm volatile("cp.async.cg.shared.global [%0], [%1], 16;\n" :: "r"(smem_u32), "l"(gmem));
}
__device__ __forceinline__ void cp_commit() { asm volatile("cp.async.commit_group;\n"); }

__device__ __forceinline__ void ldsm4(uint32_t& r0, uint32_t& r1, uint32_t& r2, uint32_t& r3,
                                      uint32_t addr)
{
    asm volatile("ldmatrix.sync.aligned.m8n8.x4.shared.b16 {%0,%1,%2,%3},[%4];\n"
                 : "=r"(r0), "=r"(r1), "=r"(r2), "=r"(r3) : "r"(addr));
}
__device__ __forceinline__ void ldsm4t(uint32_t& r0, uint32_t& r1, uint32_t& r2, uint32_t& r3,
                                       uint32_t addr)
{
    asm volatile("ldmatrix.sync.aligned.m8n8.x4.trans.shared.b16 {%0,%1,%2,%3},[%4];\n"
                 : "=r"(r0), "=r"(r1), "=r"(r2), "=r"(r3) : "r"(addr));
}

__device__ __forceinline__ void mma16816(float* c, const uint32_t* a, const uint32_t* b)
{
    asm volatile(
        "mma.sync.aligned.m16n8k16.row.col.f32.bf16.bf16.f32 "
        "{%0,%1,%2,%3},{%4,%5,%6,%7},{%8,%9},{%0,%1,%2,%3};\n"
        : "+f"(c[0]), "+f"(c[1]), "+f"(c[2]), "+f"(c[3])
        : "r"(a[0]), "r"(a[1]), "r"(a[2]), "r"(a[3]), "r"(b[0]), "r"(b[1]));
}

__device__ __forceinline__ unsigned pack_bf2(float a, float b)
{
    __nv_bfloat162 t = __floats2bfloat162_rn(a, b);
    return *reinterpret_cast<unsigned*>(&t);
}

/* ------------------------- weight abs-mean reduction (all 4 fused) --------- */
__global__ void k_absmean_all(const float* __restrict__ w0, const float* __restrict__ w1,
                              const float* __restrict__ w2, const float* __restrict__ w3,
                              double* __restrict__ part)
{
    __shared__ double sm[256];
    const float* ws[4] = {w0, w1, w2, w3};
    const float4* w4 = (const float4*)ws[blockIdx.y];
    const int n4 = CC*CC/4;
    double s = 0.0;
    for (int i = blockIdx.x*256 + threadIdx.x; i < n4; i += 64*256) {
        float4 v = w4[i];
        s += (double)fabsf(v.x) + (double)fabsf(v.y) + (double)fabsf(v.z) + (double)fabsf(v.w);
    }
    sm[threadIdx.x] = s; __syncthreads();
    for (int o = 128; o > 0; o >>= 1) {
        if (threadIdx.x < o) sm[threadIdx.x] += sm[threadIdx.x + o];
        __syncthreads();
    }
    if (threadIdx.x == 0) part[blockIdx.y*64 + blockIdx.x] = sm[0];
}

__global__ void k_finalize_all(const double* __restrict__ part, float* __restrict__ out)
{
    int w = blockIdx.x, tid = threadIdx.x;
    double s = part[w*64 + tid] + part[w*64 + tid + 32];
    for (int o = 16; o; o >>= 1) s += __shfl_xor_sync(0xffffffffu, s, o);
    if (tid == 0) out[w] = fmaxf((float)(s / (double)(CC*CC)), EPSQ);
}

/* ------------------------- ternarize weights (all 4 fused) ----------------- */
__global__ void k_ternarize_all(const float* __restrict__ w0, const float* __restrict__ w1,
                                const float* __restrict__ w2, const float* __restrict__ w3,
                                __nv_bfloat16* __restrict__ wq, const float* __restrict__ mean)
{
    const float* ws[4] = {w0, w1, w2, w3};
    int w = blockIdx.y;
    float inv = 1.0f / mean[w];
    int i = blockIdx.x*blockDim.x + threadIdx.x;
    float4 v = ((const float4*)ws[w])[i];
    float t0 = fminf(fmaxf(rintf(v.x*inv), -1.f), 1.f);
    float t1 = fminf(fmaxf(rintf(v.y*inv), -1.f), 1.f);
    float t2 = fminf(fmaxf(rintf(v.z*inv), -1.f), 1.f);
    float t3 = fminf(fmaxf(rintf(v.w*inv), -1.f), 1.f);
    uint2 u; u.x = pack_bf2(t0,t1); u.y = pack_bf2(t2,t3);
    ((uint2*)(wq + (size_t)w*CC*CC))[i] = u;
}

/* ------------------------- per-row activation quant ------------------------ */
__global__ void k_act_quant(const float* __restrict__ x, __nv_bfloat16* __restrict__ xq,
                            float* __restrict__ ascale)
{
    int row = blockIdx.x;
    int tid = threadIdx.x;
    const float4* xr = (const float4*)(x + (size_t)row*CC);
    float4 v0 = xr[tid*2];
    float4 v1 = xr[tid*2+1];
    float m = fmaxf(fmaxf(fmaxf(fabsf(v0.x), fabsf(v0.y)), fmaxf(fabsf(v0.z), fabsf(v0.w))),
                    fmaxf(fmaxf(fabsf(v1.x), fabsf(v1.y)), fmaxf(fabsf(v1.z), fabsf(v1.w))));
    for (int o = 16; o; o >>= 1) m = fmaxf(m, __shfl_xor_sync(0xffffffffu, m, o));
    __shared__ float sm[4];
    if ((tid & 31) == 0) sm[tid >> 5] = m;
    __syncthreads();
    m = fmaxf(fmaxf(sm[0], sm[1]), fmaxf(sm[2], sm[3]));
    float cm = fmaxf(m, EPSQ);
    float s  = 127.0f / cm;
    float q0 = fminf(fmaxf(rintf(v0.x*s), -128.f), 127.f);
    float q1 = fminf(fmaxf(rintf(v0.y*s), -128.f), 127.f);
    float q2 = fminf(fmaxf(rintf(v0.z*s), -128.f), 127.f);
    float q3 = fminf(fmaxf(rintf(v0.w*s), -128.f), 127.f);
    float q4 = fminf(fmaxf(rintf(v1.x*s), -128.f), 127.f);
    float q5 = fminf(fmaxf(rintf(v1.y*s), -128.f), 127.f);
    float q6 = fminf(fmaxf(rintf(v1.z*s), -128.f), 127.f);
    float q7 = fminf(fmaxf(rintf(v1.w*s), -128.f), 127.f);
    uint4 u;
    u.x = pack_bf2(q0,q1); u.y = pack_bf2(q2,q3);
    u.z = pack_bf2(q4,q5); u.w = pack_bf2(q6,q7);
    *(uint4*)(xq + (size_t)row*CC + tid*8) = u;
    if (tid == 0) ascale[row] = cm * (1.0f/127.0f);
}

/* ------------------------- bf16 tensor-core GEMM --------------------------- */
/* 4 warps, 2x2 warp grid, 64x64 warp tile: 128 B of LDSM traffic per MMA     */
/* (vs 192 with 32x64 tiles) -- smem-crossbar relief.                         */
/* split==0: Cout=f0 gets float (+bias). split==1: writes hi/lo bf16 planes.  */
#define GBM 128
#define GBN 128
#define GBK 64
#define GSTR 72
#define STAGE_ELEMS (128*GSTR)

__global__ __launch_bounds__(128) void k_gemm(
    const __nv_bfloat16* __restrict__ A, const __nv_bfloat16* __restrict__ Bw,
    float* __restrict__ f0,
    __nv_bfloat16* __restrict__ hi0, __nv_bfloat16* __restrict__ lo0,
    __nv_bfloat16* __restrict__ hi1, __nv_bfloat16* __restrict__ lo1,
    __nv_bfloat16* __restrict__ hi2, __nv_bfloat16* __restrict__ lo2,
    const float* __restrict__ ascale, const float* __restrict__ wmean,
    const float* __restrict__ bias, int split)
{
    extern __shared__ __nv_bfloat16 smem[];
    __nv_bfloat16* sA = smem;
    __nv_bfloat16* sB = smem + 2*STAGE_ELEMS;

    const int tid  = threadIdx.x;
    const int m0   = blockIdx.y*GBM;
    const int n0g  = blockIdx.x*GBN;
    const int which= n0g >> 10;
    const int n0   = n0g & 1023;
    __nv_bfloat16* HI = (which == 0) ? hi0 : (which == 1) ? hi1 : hi2;
    __nv_bfloat16* LO = (which == 0) ? lo0 : (which == 1) ? lo1 : lo2;

    const int wid  = tid >> 5, lane = tid & 31;
    const int wm_  = wid & 1, wn_ = wid >> 1;      /* 2x2 warp grid */
    const int g    = lane >> 2, t = lane & 3;

    const uint32_t sAu = (uint32_t)__cvta_generic_to_shared(sA);
    const uint32_t sBu = (uint32_t)__cvta_generic_to_shared(sB);

    const int aRow = lane & 15;
    const int aCol = (lane >> 4) << 3;
    const int bRow = (lane & 7) + ((lane & 16) ? 8 : 0);
    const int bCol = (lane & 8) ? 8 : 0;

    /* cp.async coords: 8 threads/row x 16B; 128 threads -> 16 rows per pass */
    const int ldR = tid >> 3;              /* 0..15 */
    const int ldC = (tid & 7) * 8;

    float acc[4][8][4];
    #pragma unroll
    for (int mi=0;mi<4;mi++)
        #pragma unroll
        for (int nj=0;nj<8;nj++)
            #pragma unroll
            for (int q=0;q<4;q++) acc[mi][nj][q] = 0.f;

    {
        #pragma unroll
        for (int i=0;i<8;i++) {
            int r = ldR + i*16;
            cp16(sAu + (uint32_t)((r*GSTR + ldC)*2),
                 A  + (size_t)(m0 + r)*CC + ldC);
            cp16(sBu + (uint32_t)((r*GSTR + ldC)*2),
                 Bw + (size_t)(n0g + r)*CC + ldC);
        }
        cp_commit();
    }

    const int NT = CC / GBK;
    for (int kt = 0; kt < NT; kt++) {
        asm volatile("cp.async.wait_group 0;\n");
        __syncthreads();
        const int s  = kt & 1;
        const int sn = s ^ 1;
        if (kt + 1 < NT) {
            int kb = (kt+1)*GBK;
            #pragma unroll
            for (int i=0;i<8;i++) {
                int r = ldR + i*16;
                cp16(sAu + (uint32_t)((sn*STAGE_ELEMS + r*GSTR + ldC)*2),
                     A  + (size_t)(m0 + r)*CC + kb + ldC);
                cp16(sBu + (uint32_t)((sn*STAGE_ELEMS + r*GSTR + ldC)*2),
                     Bw + (size_t)(n0g + r)*CC + kb + ldC);
            }
            cp_commit();
        }
        const uint32_t aBase = sAu + (uint32_t)(s*STAGE_ELEMS*2);
        const uint32_t bBase = sBu + (uint32_t)(s*STAGE_ELEMS*2);
        #pragma unroll
        for (int kk = 0; kk < 4; kk++) {
            const int k0 = kk*16;
            uint32_t af[4][4], bf[8][2];
            #pragma unroll
            for (int mi=0;mi<4;mi++) {
                int rb = wm_*64 + mi*16;
                ldsm4(af[mi][0], af[mi][1], af[mi][2], af[mi][3],
                      aBase + (uint32_t)((((rb + aRow)*GSTR) + k0 + aCol)*2));
            }
            #pragma unroll
            for (int p=0;p<4;p++) {
                int nb0 = wn_*64 + p*16;
                uint32_t r0,r1,r2,r3;
                ldsm4(r0, r1, r2, r3,
                      bBase + (uint32_t)((((nb0 + bRow)*GSTR) + k0 + bCol)*2));
                bf[2*p][0] = r0; bf[2*p][1] = r1;
                bf[2*p+1][0] = r2; bf[2*p+1][1] = r3;
            }
            #pragma unroll
            for (int mi=0;mi<4;mi++)
                #pragma unroll
                for (int nj=0;nj<8;nj++)
                    mma16816(acc[mi][nj], af[mi], bf[nj]);
        }
    }

    const float wm = wmean[which];
    #pragma unroll
    for (int mi=0;mi<4;mi++) {
        int r0 = m0 + wm_*64 + mi*16 + g;
        float sc0 = ascale[r0]  * wm;
        float sc1 = ascale[r0+8]* wm;
        #pragma unroll
        for (int nj=0;nj<8;nj++) {
            int cidx = n0 + wn_*64 + nj*8 + 2*t;
            float v00 = acc[mi][nj][0]*sc0, v01 = acc[mi][nj][1]*sc0;
            float v10 = acc[mi][nj][2]*sc1, v11 = acc[mi][nj][3]*sc1;
            if (split) {
                float h00 = __bfloat162float(__float2bfloat16(v00));
                float h01 = __bfloat162float(__float2bfloat16(v01));
                float h10 = __bfloat162float(__float2bfloat16(v10));
                float h11 = __bfloat162float(__float2bfloat16(v11));
                *(uint32_t*)&HI[(size_t)r0*CC     + cidx] = pack_bf2(v00, v01);
                *(uint32_t*)&LO[(size_t)r0*CC     + cidx] = pack_bf2(v00-h00, v01-h01);
                *(uint32_t*)&HI[(size_t)(r0+8)*CC + cidx] = pack_bf2(v10, v11);
                *(uint32_t*)&LO[(size_t)(r0+8)*CC + cidx] = pack_bf2(v10-h10, v11-h11);
            } else {
                float b0 = bias ? bias[cidx]   : 0.f;
                float b1 = bias ? bias[cidx+1] : 0.f;
                f0[(size_t)r0*CC     + cidx  ] = v00 + b0;
                f0[(size_t)r0*CC     + cidx+1] = v01 + b1;
                f0[(size_t)(r0+8)*CC + cidx  ] = v10 + b0;
                f0[(size_t)(r0+8)*CC + cidx+1] = v11 + b1;
            }
        }
    }
}

/* ------------------------- bf16 hi/lo flash attention ---------------------- */
/* grid (qt,h,b); 128 threads = 4 warps, warp w owns query rows w*16..w*16+15 */
#define AS 72                     /* bf16 row stride */
#define APLANE (64*AS)
#define PBYTES (APLANE*2)         /* 9216 */
#define ATTN_SMEM (12*PBYTES)     /* 110592 */

__global__ __launch_bounds__(128) void k_attn_bf(
    const __nv_bfloat16* __restrict__ Qh, const __nv_bfloat16* __restrict__ Ql,
    const __nv_bfloat16* __restrict__ Kh, const __nv_bfloat16* __restrict__ Kl,
    const __nv_bfloat16* __restrict__ Vh, const __nv_bfloat16* __restrict__ Vl,
    float* __restrict__ Y)
{
    extern __shared__ __nv_bfloat16 bsm[];
    __nv_bfloat16* sPh = bsm + 10*APLANE;
    __nv_bfloat16* sPl = bsm + 11*APLANE;

    const uint32_t u0  = (uint32_t)__cvta_generic_to_shared(bsm);
    const uint32_t uKh = u0;
    const uint32_t uKl = u0 + 2*PBYTES;
    const uint32_t uVh = u0 + 4*PBYTES;
    const uint32_t uVl = u0 + 6*PBYTES;
    const uint32_t uQh = u0 + 8*PBYTES;
    const uint32_t uQl = u0 + 9*PBYTES;
    const uint32_t uPh = u0 + 10*PBYTES;
    const uint32_t uPl = u0 + 11*PBYTES;

    const int tid = threadIdx.x;
    const int w   = tid >> 5, lane = tid & 31;
    const int g   = lane >> 2, t = lane & 3;
    const int qt  = blockIdx.x, h = blockIdx.y, b = blockIdx.z;
    const int nchunk = qt + 1;
    const size_t qrow0 = (size_t)b*TT + qt*64;
    const size_t krow0 = (size_t)b*TT;
    const int col0 = h*HD;

    const int aRow  = lane & 15;
    const int aColB = (lane >> 4) * 16;
    const int bRow  = (lane & 7) + ((lane & 16) ? 8 : 0);
    const int bColB = (lane & 8) ? 16 : 0;

    const int lrow = tid >> 3;
    const int lcolB = (tid & 7) * 16;

    #define LD_PLANE(sbase, gptr, grow0)                                        \
        do { _Pragma("unroll")                                                  \
            for (int p_ = 0; p_ < 4; p_++) {                                    \
                int r_ = lrow + p_*16;                                          \
                cp16((sbase) + (uint32_t)(r_*(AS*2) + lcolB),                   \
                     (const char*)(gptr) + (((grow0) + r_)*CC + col0)*2 + lcolB);\
            }                                                                   \
        } while (0)

    LD_PLANE(uKh, Kh, krow0);
    LD_PLANE(uKl, Kl, krow0);
    LD_PLANE(uVh, Vh, krow0);
    LD_PLANE(uVl, Vl, krow0);
    LD_PLANE(uQh, Qh, qrow0);
    LD_PLANE(uQl, Ql, qrow0);
    cp_commit();
    asm volatile("cp.async.wait_group 0;\n");
    __syncthreads();

    uint32_t qhf[4][4], qlf[4][4];
    {
        const int ra = w*16;
        #pragma unroll
        for (int ks=0;ks<4;ks++) {
            uint32_t ad = (uint32_t)(((ra + aRow)*AS)*2 + ks*32 + aColB);
            ldsm4(qhf[ks][0], qhf[ks][1], qhf[ks][2], qhf[ks][3], uQh + ad);
            ldsm4(qlf[ks][0], qlf[ks][1], qlf[ks][2], qlf[ks][3], uQl + ad);
        }
    }

    float oacc[8][4];
    #pragma unroll
    for (int nt=0;nt<8;nt++)
        #pragma unroll
        for (int q=0;q<4;q++) oacc[nt][q] = 0.f;
    float mg = -INFINITY, mg8 = -INFINITY, lg = 0.f, lg8 = 0.f;

    for (int kc = 0; kc < nchunk; kc++) {
        const int buf = kc & 1;
        if (kc + 1 < nchunk) {
            const uint32_t nb = (uint32_t)(((kc+1) & 1) * PBYTES);
            const size_t nr = krow0 + (kc+1)*64;
            LD_PLANE(uKh + nb, Kh, nr);
            LD_PLANE(uKl + nb, Kl, nr);
            LD_PLANE(uVh + nb, Vh, nr);
            LD_PLANE(uVl + nb, Vl, nr);
            cp_commit();
            asm volatile("cp.async.wait_group 1;\n");
        } else {
            asm volatile("cp.async.wait_group 0;\n");
        }
        __syncthreads();

        const uint32_t kb_h = uKh + buf*PBYTES;
        const uint32_t kb_l = uKl + buf*PBYTES;
        const uint32_t vb_h = uVh + buf*PBYTES;
        const uint32_t vb_l = uVl + buf*PBYTES;

        float sacc[8][4];
        #pragma unroll
        for (int nt=0;nt<8;nt++)
            #pragma unroll
            for (int q=0;q<4;q++) sacc[nt][q] = 0.f;
        #pragma unroll
        for (int ks=0;ks<4;ks++) {
            #pragma unroll
            for (int p=0;p<4;p++) {
                uint32_t ad = (uint32_t)(((p*16 + bRow)*AS)*2 + ks*32 + bColB);
                uint32_t bh[4], bl[4];
                ldsm4(bh[0], bh[1], bh[2], bh[3], kb_h + ad);
                ldsm4(bl[0], bl[1], bl[2], bl[3], kb_l + ad);
                mma16816(sacc[2*p  ], qhf[ks], bh    );
                mma16816(sacc[2*p  ], qhf[ks], bl    );
                mma16816(sacc[2*p  ], qlf[ks], bh    );
                mma16816(sacc[2*p+1], qhf[ks], bh + 2);
                mma16816(sacc[2*p+1], qhf[ks], bl + 2);
                mma16816(sacc[2*p+1], qlf[ks], bh + 2);
            }
        }

        const bool diag = (kc == qt);
        const int qlr  = w*16 + g;
        const int qlr8 = qlr + 8;
        #pragma unroll
        for (int nt=0;nt<8;nt++) {
            int kl0 = nt*8 + 2*t, kl1 = kl0 + 1;
            sacc[nt][0] = (diag && kl0 > qlr ) ? -INFINITY : sacc[nt][0]*0.125f;
            sacc[nt][1] = (diag && kl1 > qlr ) ? -INFINITY : sacc[nt][1]*0.125f;
            sacc[nt][2] = (diag && kl0 > qlr8) ? -INFINITY : sacc[nt][2]*0.125f;
            sacc[nt][3] = (diag && kl1 > qlr8) ? -INFINITY : sacc[nt][3]*0.125f;
        }

        float cm = -INFINITY, cm8 = -INFINITY;
        #pragma unroll
        for (int nt=0;nt<8;nt++) {
            cm  = fmaxf(cm,  fmaxf(sacc[nt][0], sacc[nt][1]));
            cm8 = fmaxf(cm8, fmaxf(sacc[nt][2], sacc[nt][3]));
        }
        #pragma unroll
        for (int o=1;o<4;o<<=1) {
            cm  = fmaxf(cm,  __shfl_xor_sync(0xffffffffu, cm,  o));
            cm8 = fmaxf(cm8, __shfl_xor_sync(0xffffffffu, cm8, o));
        }
        float nm  = fmaxf(mg,  cm);
        float nm8 = fmaxf(mg8, cm8);
        float sc  = __expf(mg  - nm);
        float sc8 = __expf(mg8 - nm8);
        mg = nm; mg8 = nm8;

        float rs = 0.f, rs8 = 0.f;
        const int pr = w*16 + g;
        #pragma unroll
        for (int nt=0;nt<8;nt++) {
            float e0 = __expf(sacc[nt][0] - nm);
            float e1 = __expf(sacc[nt][1] - nm);
            float e2 = __expf(sacc[nt][2] - nm8);
            float e3 = __expf(sacc[nt][3] - nm8);
            rs  += e0 + e1;  rs8 += e2 + e3;
            float h0 = __bfloat162float(__float2bfloat16(e0));
            float h1 = __bfloat162float(__float2bfloat16(e1));
            float h2 = __bfloat162float(__float2bfloat16(e2));
            float h3 = __bfloat162float(__float2bfloat16(e3));
            *(uint32_t*)&sPh[(pr  )*AS + nt*8 + 2*t] = pack_bf2(e0, e1);
            *(uint32_t*)&sPl[(pr  )*AS + nt*8 + 2*t] = pack_bf2(e0-h0, e1-h1);
            *(uint32_t*)&sPh[(pr+8)*AS + nt*8 + 2*t] = pack_bf2(e2, e3);
            *(uint32_t*)&sPl[(pr+8)*AS + nt*8 + 2*t] = pack_bf2(e2-h2, e3-h3);
        }
        #pragma unroll
        for (int o=1;o<4;o<<=1) {
            rs  += __shfl_xor_sync(0xffffffffu, rs,  o);
            rs8 += __shfl_xor_sync(0xffffffffu, rs8, o);
        }
        lg  = lg *sc  + rs;
        lg8 = lg8*sc8 + rs8;

        #pragma unroll
        for (int nt=0;nt<8;nt++) {
            oacc[nt][0] *= sc;  oacc[nt][1] *= sc;
            oacc[nt][2] *= sc8; oacc[nt][3] *= sc8;
        }
        __syncwarp();

        #pragma unroll
        for (int ks=0;ks<4;ks++) {
            uint32_t pa[4], pb[4];
            uint32_t pad = (uint32_t)(((w*16 + aRow)*AS)*2 + ks*32 + aColB);
            ldsm4(pa[0], pa[1], pa[2], pa[3], uPh + pad);
            ldsm4(pb[0], pb[1], pb[2], pb[3], uPl + pad);
            #pragma unroll
            for (int p=0;p<4;p++) {
                uint32_t vd = (uint32_t)(((ks*16 + aRow)*AS)*2 + p*32 + aColB);
                uint32_t vh[4], vl[4];
                ldsm4t(vh[0], vh[1], vh[2], vh[3], vb_h + vd);
                ldsm4t(vl[0], vl[1], vl[2], vl[3], vb_l + vd);
                mma16816(oacc[2*p  ], pa, vh    );
                mma16816(oacc[2*p  ], pa, vl    );
                mma16816(oacc[2*p  ], pb, vh    );
                mma16816(oacc[2*p+1], pa, vh + 2);
                mma16816(oacc[2*p+1], pa, vl + 2);
                mma16816(oacc[2*p+1], pb, vh + 2);
            }
        }
        __syncthreads();    /* all K/V/P reads done before next chunk's loads */
    }

    float inv  = 1.0f/lg;
    float inv8 = 1.0f/lg8;
    const size_t r0 = qrow0 + w*16 + g;
    #pragma unroll
    for (int nt=0;nt<8;nt++) {
        float2 o0; o0.x = oacc[nt][0]*inv;  o0.y = oacc[nt][1]*inv;
        float2 o1; o1.x = oacc[nt][2]*inv8; o1.y = oacc[nt][3]*inv8;
        *(float2*)&Y[(r0    )*CC + col0 + nt*8 + 2*t] = o0;
        *(float2*)&Y[(r0 + 8)*CC + col0 + nt*8 + 2*t] = o1;
    }
}

/* ------------------------- launch --------------------------------------- */
extern "C" void kernel_launch(void* const* d_in, const int* in_sizes, int n_in,
                              void* d_out, int out_size)
{
    const float* x  = (const float*)d_in[0];
    const float* W0 = (const float*)d_in[1];
    const float* W1 = (const float*)d_in[2];
    const float* W2 = (const float*)d_in[3];
    const float* W3 = (const float*)d_in[4];
    const float* bp = (const float*)d_in[5];

    float* wmean;   cudaGetSymbolAddress((void**)&wmean,  g_wmean);
    double* part;   cudaGetSymbolAddress((void**)&part,   g_partial);
    __nv_bfloat16* wq;  cudaGetSymbolAddress((void**)&wq,  g_wq);
    __nv_bfloat16* xq;  cudaGetSymbolAddress((void**)&xq,  g_xq);
    float* ascale;  cudaGetSymbolAddress((void**)&ascale, g_ascale);
    __nv_bfloat16* qhi; cudaGetSymbolAddress((void**)&qhi, g_qhi);
    __nv_bfloat16* qlo; cudaGetSymbolAddress((void**)&qlo, g_qlo);
    __nv_bfloat16* khi; cudaGetSymbolAddress((void**)&khi, g_khi);
    __nv_bfloat16* klo; cudaGetSymbolAddress((void**)&klo, g_klo);
    __nv_bfloat16* vhi; cudaGetSymbolAddress((void**)&vhi, g_vhi);
    __nv_bfloat16* vlo; cudaGetSymbolAddress((void**)&vlo, g_vlo);
    float* yb;      cudaGetSymbolAddress((void**)&yb,     g_yb);
    __nv_bfloat16* yq;  cudaGetSymbolAddress((void**)&yq,  g_yq);
    float* yscale;  cudaGetSymbolAddress((void**)&yscale, g_yscale);

    const int GEMM_SMEM = 4*STAGE_ELEMS*(int)sizeof(__nv_bfloat16);   /* 73728 */
    cudaFuncSetAttribute(k_gemm,    cudaFuncAttributeMaxDynamicSharedMemorySize, GEMM_SMEM);
    cudaFuncSetAttribute(k_attn_bf, cudaFuncAttributeMaxDynamicSharedMemorySize, ATTN_SMEM);

    k_absmean_all  <<<dim3(64,4), 256>>>(W0, W1, W2, W3, part);
    k_finalize_all <<<4, 32>>>(part, wmean);
    k_ternarize_all<<<dim3(1024,4), 256>>>(W0, W1, W2, W3, wq, wmean);

    k_act_quant<<<MM, 128>>>(x, xq, ascale);

    /* fused QKV GEMM: N = 3072; outputs split to bf16 hi/lo planes */
    dim3 gqkv(3*CC/GBN, MM/GBM);   /* (24, 128) */
    k_gemm<<<gqkv, 128, GEMM_SMEM>>>(xq, wq, nullptr,
                                     qhi, qlo, khi, klo, vhi, vlo,
                                     ascale, wmean, nullptr, 1);

    dim3 agrid(TT/64, HH, BB);     /* (4, 16, 64) */
    k_attn_bf<<<agrid, 128, ATTN_SMEM>>>(qhi, qlo, khi, klo, vhi, vlo, yb);

    k_act_quant<<<MM, 128>>>(yb, yq, yscale);

    /* projection GEMM: N = 1024, fp32 out + bias */
    dim3 gproj(CC/GBN, MM/GBM);    /* (8, 128) */
    k_gemm<<<gproj, 128, GEMM_SMEM>>>(yq, wq + 3*(size_t)CC*CC, (float*)d_out,
                                      nullptr, nullptr, nullptr, nullptr, nullptr, nullptr,
                                      yscale, wmean + 3, bp, 0);
}

// round 13
// speedup vs baseline: 1.0249x; 1.0249x over previous
#include <cuda_runtime.h>
#include <cuda_bf16.h>
#include <math.h>
#include <stdint.h>

#define BB 64
#define TT 256
#define CC 1024
#define HH 16
#define HD 64
#define MM (BB*TT)      /* 16384 rows */
#define EPSQ 1e-5f

/* ------------------------- scratch (static device globals) ----------------- */
__device__ float          g_wmean[4];
__device__ double         g_partial[4*64];
__device__ __nv_bfloat16  g_wq[4][CC*CC];
__device__ __nv_bfloat16  g_xq[MM*CC];
__device__ float          g_ascale[MM];
__device__ __nv_bfloat16  g_qhi[MM*CC];
__device__ __nv_bfloat16  g_qlo[MM*CC];
__device__ __nv_bfloat16  g_khi[MM*CC];
__device__ __nv_bfloat16  g_klo[MM*CC];
__device__ __nv_bfloat16  g_vhi[MM*CC];
__device__ __nv_bfloat16  g_vlo[MM*CC];
__device__ float          g_yb[MM*CC];
__device__ __nv_bfloat16  g_yq[MM*CC];
__device__ float          g_yscale[MM];

/* ------------------------- PTX helpers ------------------------------------ */
__device__ __forceinline__ void cp16(uint32_t smem_u32, const void* gmem)
{
    asm volatile("cp.async.cg.shared.global [%0], [%1], 16;\n" :: "r"(smem_u32), "l"(gmem));
}
__device__ __forceinline__ void cp_commit() { asm volatile("cp.async.commit_group;\n"); }

__device__ __forceinline__ void ldsm4(uint32_t& r0, uint32_t& r1, uint32_t& r2, uint32_t& r3,
                                      uint32_t addr)
{
    asm volatile("ldmatrix.sync.aligned.m8n8.x4.shared.b16 {%0,%1,%2,%3},[%4];\n"
                 : "=r"(r0), "=r"(r1), "=r"(r2), "=r"(r3) : "r"(addr));
}
__device__ __forceinline__ void ldsm4t(uint32_t& r0, uint32_t& r1, uint32_t& r2, uint32_t& r3,
                                       uint32_t addr)
{
    asm volatile("ldmatrix.sync.aligned.m8n8.x4.trans.shared.b16 {%0,%1,%2,%3},[%4];\n"
                 : "=r"(r0), "=r"(r1), "=r"(r2), "=r"(r3) : "r"(addr));
}

__device__ __forceinline__ void mma16816(float* c, const uint32_t* a, const uint32_t* b)
{
    asm volatile(
        "mma.sync.aligned.m16n8k16.row.col.f32.bf16.bf16.f32 "
        "{%0,%1,%2,%3},{%4,%5,%6,%7},{%8,%9},{%0,%1,%2,%3};\n"
        : "+f"(c[0]), "+f"(c[1]), "+f"(c[2]), "+f"(c[3])
        : "r"(a[0]), "r"(a[1]), "r"(a[2]), "r"(a[3]), "r"(b[0]), "r"(b[1]));
}

__device__ __forceinline__ unsigned pack_bf2(float a, float b)
{
    __nv_bfloat162 t = __floats2bfloat162_rn(a, b);
    return *reinterpret_cast<unsigned*>(&t);
}

/* ------------------------- weight abs-mean reduction (all 4 fused) --------- */
__global__ void k_absmean_all(const float* __restrict__ w0, const float* __restrict__ w1,
                              const float* __restrict__ w2, const float* __restrict__ w3,
                              double* __restrict__ part)
{
    __shared__ double sm[256];
    const float* ws[4] = {w0, w1, w2, w3};
    const float4* w4 = (const float4*)ws[blockIdx.y];
    const int n4 = CC*CC/4;
    double s = 0.0;
    for (int i = blockIdx.x*256 + threadIdx.x; i < n4; i += 64*256) {
        float4 v = w4[i];
        s += (double)fabsf(v.x) + (double)fabsf(v.y) + (double)fabsf(v.z) + (double)fabsf(v.w);
    }
    sm[threadIdx.x] = s; __syncthreads();
    for (int o = 128; o > 0; o >>= 1) {
        if (threadIdx.x < o) sm[threadIdx.x] += sm[threadIdx.x + o];
        __syncthreads();
    }
    if (threadIdx.x == 0) part[blockIdx.y*64 + blockIdx.x] = sm[0];
}

/* --------- ternarize weights; finalize of abs-mean fused in-block ---------- */
__global__ void k_ternfin_all(const float* __restrict__ w0, const float* __restrict__ w1,
                              const float* __restrict__ w2, const float* __restrict__ w3,
                              __nv_bfloat16* __restrict__ wq, const double* __restrict__ part)
{
    const float* ws[4] = {w0, w1, w2, w3};
    const int w = blockIdx.y;
    __shared__ float s_inv;
    if (threadIdx.x < 32) {
        int tid = threadIdx.x;
        double s = part[w*64 + tid] + part[w*64 + tid + 32];
        for (int o = 16; o; o >>= 1) s += __shfl_xor_sync(0xffffffffu, s, o);
        if (tid == 0)
            s_inv = 1.0f / fmaxf((float)(s / (double)(CC*CC)), EPSQ);
    }
    __syncthreads();
    float inv = s_inv;
    int i = blockIdx.x*blockDim.x + threadIdx.x;
    float4 v = ((const float4*)ws[w])[i];
    float t0 = fminf(fmaxf(rintf(v.x*inv), -1.f), 1.f);
    float t1 = fminf(fmaxf(rintf(v.y*inv), -1.f), 1.f);
    float t2 = fminf(fmaxf(rintf(v.z*inv), -1.f), 1.f);
    float t3 = fminf(fmaxf(rintf(v.w*inv), -1.f), 1.f);
    uint2 u; u.x = pack_bf2(t0,t1); u.y = pack_bf2(t2,t3);
    ((uint2*)(wq + (size_t)w*CC*CC))[i] = u;
    /* also publish wmean for the GEMM epilogues (one thread per matrix) */
    if (blockIdx.x == 0 && threadIdx.x == 0)
        g_wmean[w] = 1.0f / inv;
}

/* ------------------------- per-row activation quant ------------------------ */
__global__ void k_act_quant(const float* __restrict__ x, __nv_bfloat16* __restrict__ xq,
                            float* __restrict__ ascale)
{
    int row = blockIdx.x;
    int tid = threadIdx.x;
    const float4* xr = (const float4*)(x + (size_t)row*CC);
    float4 v0 = xr[tid*2];
    float4 v1 = xr[tid*2+1];
    float m = fmaxf(fmaxf(fmaxf(fabsf(v0.x), fabsf(v0.y)), fmaxf(fabsf(v0.z), fabsf(v0.w))),
                    fmaxf(fmaxf(fabsf(v1.x), fabsf(v1.y)), fmaxf(fabsf(v1.z), fabsf(v1.w))));
    for (int o = 16; o; o >>= 1) m = fmaxf(m, __shfl_xor_sync(0xffffffffu, m, o));
    __shared__ float sm[4];
    if ((tid & 31) == 0) sm[tid >> 5] = m;
    __syncthreads();
    m = fmaxf(fmaxf(sm[0], sm[1]), fmaxf(sm[2], sm[3]));
    float cm = fmaxf(m, EPSQ);
    float s  = 127.0f / cm;
    float q0 = fminf(fmaxf(rintf(v0.x*s), -128.f), 127.f);
    float q1 = fminf(fmaxf(rintf(v0.y*s), -128.f), 127.f);
    float q2 = fminf(fmaxf(rintf(v0.z*s), -128.f), 127.f);
    float q3 = fminf(fmaxf(rintf(v0.w*s), -128.f), 127.f);
    float q4 = fminf(fmaxf(rintf(v1.x*s), -128.f), 127.f);
    float q5 = fminf(fmaxf(rintf(v1.y*s), -128.f), 127.f);
    float q6 = fminf(fmaxf(rintf(v1.z*s), -128.f), 127.f);
    float q7 = fminf(fmaxf(rintf(v1.w*s), -128.f), 127.f);
    uint4 u;
    u.x = pack_bf2(q0,q1); u.y = pack_bf2(q2,q3);
    u.z = pack_bf2(q4,q5); u.w = pack_bf2(q6,q7);
    *(uint4*)(xq + (size_t)row*CC + tid*8) = u;
    if (tid == 0) ascale[row] = cm * (1.0f/127.0f);
}

/* ------------------------- bf16 tensor-core GEMM (R11 shape) --------------- */
/* 8 warps, 4x2 warp grid, 32x64 warp tiles; 2-stage cp.async pipeline.       */
/* split==0: Cout=f0 gets float (+bias). split==1: writes hi/lo bf16 planes.  */
#define GBM 128
#define GBN 128
#define GBK 64
#define GSTR 72
#define STAGE_ELEMS (128*GSTR)

__global__ __launch_bounds__(256) void k_gemm(
    const __nv_bfloat16* __restrict__ A, const __nv_bfloat16* __restrict__ Bw,
    float* __restrict__ f0,
    __nv_bfloat16* __restrict__ hi0, __nv_bfloat16* __restrict__ lo0,
    __nv_bfloat16* __restrict__ hi1, __nv_bfloat16* __restrict__ lo1,
    __nv_bfloat16* __restrict__ hi2, __nv_bfloat16* __restrict__ lo2,
    const float* __restrict__ ascale, const float* __restrict__ wmean,
    const float* __restrict__ bias, int split)
{
    extern __shared__ __nv_bfloat16 smem[];
    __nv_bfloat16* sA = smem;
    __nv_bfloat16* sB = smem + 2*STAGE_ELEMS;

    const int tid  = threadIdx.x;
    const int m0   = blockIdx.y*GBM;
    const int n0g  = blockIdx.x*GBN;
    const int which= n0g >> 10;
    const int n0   = n0g & 1023;
    __nv_bfloat16* HI = (which == 0) ? hi0 : (which == 1) ? hi1 : hi2;
    __nv_bfloat16* LO = (which == 0) ? lo0 : (which == 1) ? lo1 : lo2;

    const int wid  = tid >> 5, lane = tid & 31;
    const int wm_  = wid & 3, wn_ = wid >> 2;
    const int g    = lane >> 2, t = lane & 3;

    const uint32_t sAu = (uint32_t)__cvta_generic_to_shared(sA);
    const uint32_t sBu = (uint32_t)__cvta_generic_to_shared(sB);

    const int aRow = lane & 15;
    const int aCol = (lane >> 4) << 3;
    const int bRow = (lane & 7) + ((lane & 16) ? 8 : 0);
    const int bCol = (lane & 8) ? 8 : 0;

    const int ldR = tid >> 3;
    const int ldC = (tid & 7) * 8;

    float acc[2][8][4];
    #pragma unroll
    for (int mi=0;mi<2;mi++)
        #pragma unroll
        for (int nj=0;nj<8;nj++)
            #pragma unroll
            for (int q=0;q<4;q++) acc[mi][nj][q] = 0.f;

    {
        #pragma unroll
        for (int i=0;i<4;i++) {
            int r = ldR + i*32;
            cp16(sAu + (uint32_t)((r*GSTR + ldC)*2),
                 A  + (size_t)(m0 + r)*CC + ldC);
            cp16(sBu + (uint32_t)((r*GSTR + ldC)*2),
                 Bw + (size_t)(n0g + r)*CC + ldC);
        }
        cp_commit();
    }

    const int NT = CC / GBK;
    for (int kt = 0; kt < NT; kt++) {
        asm volatile("cp.async.wait_group 0;\n");
        __syncthreads();
        const int s  = kt & 1;
        const int sn = s ^ 1;
        if (kt + 1 < NT) {
            int kb = (kt+1)*GBK;
            #pragma unroll
            for (int i=0;i<4;i++) {
                int r = ldR + i*32;
                cp16(sAu + (uint32_t)((sn*STAGE_ELEMS + r*GSTR + ldC)*2),
                     A  + (size_t)(m0 + r)*CC + kb + ldC);
                cp16(sBu + (uint32_t)((sn*STAGE_ELEMS + r*GSTR + ldC)*2),
                     Bw + (size_t)(n0g + r)*CC + kb + ldC);
            }
            cp_commit();
        }
        const uint32_t aBase = sAu + (uint32_t)(s*STAGE_ELEMS*2);
        const uint32_t bBase = sBu + (uint32_t)(s*STAGE_ELEMS*2);
        #pragma unroll
        for (int kk = 0; kk < 4; kk++) {
            const int k0 = kk*16;
            uint32_t af[2][4], bf[8][2];
            #pragma unroll
            for (int mi=0;mi<2;mi++) {
                int rb = wm_*32 + mi*16;
                ldsm4(af[mi][0], af[mi][1], af[mi][2], af[mi][3],
                      aBase + (uint32_t)((((rb + aRow)*GSTR) + k0 + aCol)*2));
            }
            #pragma unroll
            for (int p=0;p<4;p++) {
                int nb0 = wn_*64 + p*16;
                uint32_t r0,r1,r2,r3;
                ldsm4(r0, r1, r2, r3,
                      bBase + (uint32_t)((((nb0 + bRow)*GSTR) + k0 + bCol)*2));
                bf[2*p][0] = r0; bf[2*p][1] = r1;
                bf[2*p+1][0] = r2; bf[2*p+1][1] = r3;
            }
            #pragma unroll
            for (int mi=0;mi<2;mi++)
                #pragma unroll
                for (int nj=0;nj<8;nj++)
                    mma16816(acc[mi][nj], af[mi], bf[nj]);
        }
    }

    const float wm = wmean[which];
    #pragma unroll
    for (int mi=0;mi<2;mi++) {
        int r0 = m0 + wm_*32 + mi*16 + g;
        float sc0 = ascale[r0]  * wm;
        float sc1 = ascale[r0+8]* wm;
        #pragma unroll
        for (int nj=0;nj<8;nj++) {
            int cidx = n0 + wn_*64 + nj*8 + 2*t;
            float v00 = acc[mi][nj][0]*sc0, v01 = acc[mi][nj][1]*sc0;
            float v10 = acc[mi][nj][2]*sc1, v11 = acc[mi][nj][3]*sc1;
            if (split) {
                float h00 = __bfloat162float(__float2bfloat16(v00));
                float h01 = __bfloat162float(__float2bfloat16(v01));
                float h10 = __bfloat162float(__float2bfloat16(v10));
                float h11 = __bfloat162float(__float2bfloat16(v11));
                *(uint32_t*)&HI[(size_t)r0*CC     + cidx] = pack_bf2(v00, v01);
                *(uint32_t*)&LO[(size_t)r0*CC     + cidx] = pack_bf2(v00-h00, v01-h01);
                *(uint32_t*)&HI[(size_t)(r0+8)*CC + cidx] = pack_bf2(v10, v11);
                *(uint32_t*)&LO[(size_t)(r0+8)*CC + cidx] = pack_bf2(v10-h10, v11-h11);
            } else {
                float b0 = bias ? bias[cidx]   : 0.f;
                float b1 = bias ? bias[cidx+1] : 0.f;
                f0[(size_t)r0*CC     + cidx  ] = v00 + b0;
                f0[(size_t)r0*CC     + cidx+1] = v01 + b1;
                f0[(size_t)(r0+8)*CC + cidx  ] = v10 + b0;
                f0[(size_t)(r0+8)*CC + cidx+1] = v11 + b1;
            }
        }
    }
}

/* ------------------------- bf16 hi/lo flash attention ---------------------- */
/* grid (qt,h,b); 128 threads = 4 warps, warp w owns query rows w*16..w*16+15 */
#define AS 72                     /* bf16 row stride */
#define APLANE (64*AS)
#define PBYTES (APLANE*2)         /* 9216 */
#define ATTN_SMEM (12*PBYTES)     /* 110592 */

__global__ __launch_bounds__(128) void k_attn_bf(
    const __nv_bfloat16* __restrict__ Qh, const __nv_bfloat16* __restrict__ Ql,
    const __nv_bfloat16* __restrict__ Kh, const __nv_bfloat16* __restrict__ Kl,
    const __nv_bfloat16* __restrict__ Vh, const __nv_bfloat16* __restrict__ Vl,
    float* __restrict__ Y)
{
    extern __shared__ __nv_bfloat16 bsm[];
    __nv_bfloat16* sPh = bsm + 10*APLANE;
    __nv_bfloat16* sPl = bsm + 11*APLANE;

    const uint32_t u0  = (uint32_t)__cvta_generic_to_shared(bsm);
    const uint32_t uKh = u0;
    const uint32_t uKl = u0 + 2*PBYTES;
    const uint32_t uVh = u0 + 4*PBYTES;
    const uint32_t uVl = u0 + 6*PBYTES;
    const uint32_t uQh = u0 + 8*PBYTES;
    const uint32_t uQl = u0 + 9*PBYTES;
    const uint32_t uPh = u0 + 10*PBYTES;
    const uint32_t uPl = u0 + 11*PBYTES;

    const int tid = threadIdx.x;
    const int w   = tid >> 5, lane = tid & 31;
    const int g   = lane >> 2, t = lane & 3;
    const int qt  = blockIdx.x, h = blockIdx.y, b = blockIdx.z;
    const int nchunk = qt + 1;
    const size_t qrow0 = (size_t)b*TT + qt*64;
    const size_t krow0 = (size_t)b*TT;
    const int col0 = h*HD;

    const int aRow  = lane & 15;
    const int aColB = (lane >> 4) * 16;
    const int bRow  = (lane & 7) + ((lane & 16) ? 8 : 0);
    const int bColB = (lane & 8) ? 16 : 0;

    const int lrow = tid >> 3;
    const int lcolB = (tid & 7) * 16;

    #define LD_PLANE(sbase, gptr, grow0)                                        \
        do { _Pragma("unroll")                                                  \
            for (int p_ = 0; p_ < 4; p_++) {                                    \
                int r_ = lrow + p_*16;                                          \
                cp16((sbase) + (uint32_t)(r_*(AS*2) + lcolB),                   \
                     (const char*)(gptr) + (((grow0) + r_)*CC + col0)*2 + lcolB);\
            }                                                                   \
        } while (0)

    LD_PLANE(uKh, Kh, krow0);
    LD_PLANE(uKl, Kl, krow0);
    LD_PLANE(uVh, Vh, krow0);
    LD_PLANE(uVl, Vl, krow0);
    LD_PLANE(uQh, Qh, qrow0);
    LD_PLANE(uQl, Ql, qrow0);
    cp_commit();
    asm volatile("cp.async.wait_group 0;\n");
    __syncthreads();

    uint32_t qhf[4][4], qlf[4][4];
    {
        const int ra = w*16;
        #pragma unroll
        for (int ks=0;ks<4;ks++) {
            uint32_t ad = (uint32_t)(((ra + aRow)*AS)*2 + ks*32 + aColB);
            ldsm4(qhf[ks][0], qhf[ks][1], qhf[ks][2], qhf[ks][3], uQh + ad);
            ldsm4(qlf[ks][0], qlf[ks][1], qlf[ks][2], qlf[ks][3], uQl + ad);
        }
    }

    float oacc[8][4];
    #pragma unroll
    for (int nt=0;nt<8;nt++)
        #pragma unroll
        for (int q=0;q<4;q++) oacc[nt][q] = 0.f;
    float mg = -INFINITY, mg8 = -INFINITY, lg = 0.f, lg8 = 0.f;

    for (int kc = 0; kc < nchunk; kc++) {
        const int buf = kc & 1;
        if (kc + 1 < nchunk) {
            const uint32_t nb = (uint32_t)(((kc+1) & 1) * PBYTES);
            const size_t nr = krow0 + (kc+1)*64;
            LD_PLANE(uKh + nb, Kh, nr);
            LD_PLANE(uKl + nb, Kl, nr);
            LD_PLANE(uVh + nb, Vh, nr);
            LD_PLANE(uVl + nb, Vl, nr);
            cp_commit();
            asm volatile("cp.async.wait_group 1;\n");
        } else {
            asm volatile("cp.async.wait_group 0;\n");
        }
        __syncthreads();

        const uint32_t kb_h = uKh + buf*PBYTES;
        const uint32_t kb_l = uKl + buf*PBYTES;
        const uint32_t vb_h = uVh + buf*PBYTES;
        const uint32_t vb_l = uVl + buf*PBYTES;

        float sacc[8][4];
        #pragma unroll
        for (int nt=0;nt<8;nt++)
            #pragma unroll
            for (int q=0;q<4;q++) sacc[nt][q] = 0.f;
        #pragma unroll
        for (int ks=0;ks<4;ks++) {
            #pragma unroll
            for (int p=0;p<4;p++) {
                uint32_t ad = (uint32_t)(((p*16 + bRow)*AS)*2 + ks*32 + bColB);
                uint32_t bh[4], bl[4];
                ldsm4(bh[0], bh[1], bh[2], bh[3], kb_h + ad);
                ldsm4(bl[0], bl[1], bl[2], bl[3], kb_l + ad);
                mma16816(sacc[2*p  ], qhf[ks], bh    );
                mma16816(sacc[2*p  ], qhf[ks], bl    );
                mma16816(sacc[2*p  ], qlf[ks], bh    );
                mma16816(sacc[2*p+1], qhf[ks], bh + 2);
                mma16816(sacc[2*p+1], qhf[ks], bl + 2);
                mma16816(sacc[2*p+1], qlf[ks], bh + 2);
            }
        }

        const bool diag = (kc == qt);
        const int qlr  = w*16 + g;
        const int qlr8 = qlr + 8;
        #pragma unroll
        for (int nt=0;nt<8;nt++) {
            int kl0 = nt*8 + 2*t, kl1 = kl0 + 1;
            sacc[nt][0] = (diag && kl0 > qlr ) ? -INFINITY : sacc[nt][0]*0.125f;
            sacc[nt][1] = (diag && kl1 > qlr ) ? -INFINITY : sacc[nt][1]*0.125f;
            sacc[nt][2] = (diag && kl0 > qlr8) ? -INFINITY : sacc[nt][2]*0.125f;
            sacc[nt][3] = (diag && kl1 > qlr8) ? -INFINITY : sacc[nt][3]*0.125f;
        }

        float cm = -INFINITY, cm8 = -INFINITY;
        #pragma unroll
        for (int nt=0;nt<8;nt++) {
            cm  = fmaxf(cm,  fmaxf(sacc[nt][0], sacc[nt][1]));
            cm8 = fmaxf(cm8, fmaxf(sacc[nt][2], sacc[nt][3]));
        }
        #pragma unroll
        for (int o=1;o<4;o<<=1) {
            cm  = fmaxf(cm,  __shfl_xor_sync(0xffffffffu, cm,  o));
            cm8 = fmaxf(cm8, __shfl_xor_sync(0xffffffffu, cm8, o));
        }
        float nm  = fmaxf(mg,  cm);
        float nm8 = fmaxf(mg8, cm8);
        float sc  = __expf(mg  - nm);
        float sc8 = __expf(mg8 - nm8);
        mg = nm; mg8 = nm8;

        float rs = 0.f, rs8 = 0.f;
        const int pr = w*16 + g;
        #pragma unroll
        for (int nt=0;nt<8;nt++) {
            float e0 = __expf(sacc[nt][0] - nm);
            float e1 = __expf(sacc[nt][1] - nm);
            float e2 = __expf(sacc[nt][2] - nm8);
            float e3 = __expf(sacc[nt][3] - nm8);
            rs  += e0 + e1;  rs8 += e2 + e3;
            float h0 = __bfloat162float(__float2bfloat16(e0));
            float h1 = __bfloat162float(__float2bfloat16(e1));
            float h2 = __bfloat162float(__float2bfloat16(e2));
            float h3 = __bfloat162float(__float2bfloat16(e3));
            *(uint32_t*)&sPh[(pr  )*AS + nt*8 + 2*t] = pack_bf2(e0, e1);
            *(uint32_t*)&sPl[(pr  )*AS + nt*8 + 2*t] = pack_bf2(e0-h0, e1-h1);
            *(uint32_t*)&sPh[(pr+8)*AS + nt*8 + 2*t] = pack_bf2(e2, e3);
            *(uint32_t*)&sPl[(pr+8)*AS + nt*8 + 2*t] = pack_bf2(e2-h2, e3-h3);
        }
        #pragma unroll
        for (int o=1;o<4;o<<=1) {
            rs  += __shfl_xor_sync(0xffffffffu, rs,  o);
            rs8 += __shfl_xor_sync(0xffffffffu, rs8, o);
        }
        lg  = lg *sc  + rs;
        lg8 = lg8*sc8 + rs8;

        #pragma unroll
        for (int nt=0;nt<8;nt++) {
            oacc[nt][0] *= sc;  oacc[nt][1] *= sc;
            oacc[nt][2] *= sc8; oacc[nt][3] *= sc8;
        }
        __syncwarp();

        #pragma unroll
        for (int ks=0;ks<4;ks++) {
            uint32_t pa[4], pb[4];
            uint32_t pad = (uint32_t)(((w*16 + aRow)*AS)*2 + ks*32 + aColB);
            ldsm4(pa[0], pa[1], pa[2], pa[3], uPh + pad);
            ldsm4(pb[0], pb[1], pb[2], pb[3], uPl + pad);
            #pragma unroll
            for (int p=0;p<4;p++) {
                uint32_t vd = (uint32_t)(((ks*16 + aRow)*AS)*2 + p*32 + aColB);
                uint32_t vh[4], vl[4];
                ldsm4t(vh[0], vh[1], vh[2], vh[3], vb_h + vd);
                ldsm4t(vl[0], vl[1], vl[2], vl[3], vb_l + vd);
                mma16816(oacc[2*p  ], pa, vh    );
                mma16816(oacc[2*p  ], pa, vl    );
                mma16816(oacc[2*p  ], pb, vh    );
                mma16816(oacc[2*p+1], pa, vh + 2);
                mma16816(oacc[2*p+1], pa, vl + 2);
                mma16816(oacc[2*p+1], pb, vh + 2);
            }
        }
        __syncthreads();    /* all K/V/P reads done before next chunk's loads */
    }

    float inv  = 1.0f/lg;
    float inv8 = 1.0f/lg8;
    const size_t r0 = qrow0 + w*16 + g;
    #pragma unroll
    for (int nt=0;nt<8;nt++) {
        float2 o0; o0.x = oacc[nt][0]*inv;  o0.y = oacc[nt][1]*inv;
        float2 o1; o1.x = oacc[nt][2]*inv8; o1.y = oacc[nt][3]*inv8;
        *(float2*)&Y[(r0    )*CC + col0 + nt*8 + 2*t] = o0;
        *(float2*)&Y[(r0 + 8)*CC + col0 + nt*8 + 2*t] = o1;
    }
}

/* ------------------------- launch --------------------------------------- */
extern "C" void kernel_launch(void* const* d_in, const int* in_sizes, int n_in,
                              void* d_out, int out_size)
{
    const float* x  = (const float*)d_in[0];
    const float* W0 = (const float*)d_in[1];
    const float* W1 = (const float*)d_in[2];
    const float* W2 = (const float*)d_in[3];
    const float* W3 = (const float*)d_in[4];
    const float* bp = (const float*)d_in[5];

    float* wmean;   cudaGetSymbolAddress((void**)&wmean,  g_wmean);
    double* part;   cudaGetSymbolAddress((void**)&part,   g_partial);
    __nv_bfloat16* wq;  cudaGetSymbolAddress((void**)&wq,  g_wq);
    __nv_bfloat16* xq;  cudaGetSymbolAddress((void**)&xq,  g_xq);
    float* ascale;  cudaGetSymbolAddress((void**)&ascale, g_ascale);
    __nv_bfloat16* qhi; cudaGetSymbolAddress((void**)&qhi, g_qhi);
    __nv_bfloat16* qlo; cudaGetSymbolAddress((void**)&qlo, g_qlo);
    __nv_bfloat16* khi; cudaGetSymbolAddress((void**)&khi, g_khi);
    __nv_bfloat16* klo; cudaGetSymbolAddress((void**)&klo, g_klo);
    __nv_bfloat16* vhi; cudaGetSymbolAddress((void**)&vhi, g_vhi);
    __nv_bfloat16* vlo; cudaGetSymbolAddress((void**)&vlo, g_vlo);
    float* yb;      cudaGetSymbolAddress((void**)&yb,     g_yb);
    __nv_bfloat16* yq;  cudaGetSymbolAddress((void**)&yq,  g_yq);
    float* yscale;  cudaGetSymbolAddress((void**)&yscale, g_yscale);

    const int GEMM_SMEM = 4*STAGE_ELEMS*(int)sizeof(__nv_bfloat16);   /* 73728 */
    cudaFuncSetAttribute(k_gemm,    cudaFuncAttributeMaxDynamicSharedMemorySize, GEMM_SMEM);
    cudaFuncSetAttribute(k_attn_bf, cudaFuncAttributeMaxDynamicSharedMemorySize, ATTN_SMEM);

    /* prep: 2 launches (finalize fused into ternarize) */
    k_absmean_all<<<dim3(64,4), 256>>>(W0, W1, W2, W3, part);
    k_ternfin_all<<<dim3(1024,4), 256>>>(W0, W1, W2, W3, wq, part);

    k_act_quant<<<MM, 128>>>(x, xq, ascale);

    /* fused QKV GEMM: N = 3072; outputs split to bf16 hi/lo planes */
    dim3 gqkv(3*CC/GBN, MM/GBM);   /* (24, 128) */
    k_gemm<<<gqkv, 256, GEMM_SMEM>>>(xq, wq, nullptr,
                                     qhi, qlo, khi, klo, vhi, vlo,
                                     ascale, wmean, nullptr, 1);

    dim3 agrid(TT/64, HH, BB);     /* (4, 16, 64) */
    k_attn_bf<<<agrid, 128, ATTN_SMEM>>>(qhi, qlo, khi, klo, vhi, vlo, yb);

    k_act_quant<<<MM, 128>>>(yb, yq, yscale);

    /* projection GEMM: N = 1024, fp32 out + bias */
    dim3 gproj(CC/GBN, MM/GBM);    /* (8, 128) */
    k_gemm<<<gproj, 256, GEMM_SMEM>>>(yq, wq + 3*(size_t)CC*CC, (float*)d_out,
                                      nullptr, nullptr, nullptr, nullptr, nullptr, nullptr,
                                      yscale, wmean + 3, bp, 0);
}